// round 3
// baseline (speedup 1.0000x reference)
#include <cuda_runtime.h>
#include <cuda_bf16.h>
#include <cstdint>

// Problem shape (fixed by the reference):
//   B=8, K=4096, M=4096, L=K+M=8192, D=512, fp32.
// out[b, keep_ids[b,k], :] = inputs[b,k,:]
// out[b, mask_ids[b,m], :] = mask_embedding[:]
// keep/mask ids partition [0, L) per batch -> every output row written exactly once.

#define B_DIM 8
#define K_DIM 4096
#define M_DIM 4096
#define L_DIM (K_DIM + M_DIM)
#define D_DIM 512
#define VEC4_PER_ROW (D_DIM / 4)     // 128 float4 per row
#define ROWS_PER_BLOCK 2
#define THREADS (VEC4_PER_ROW * ROWS_PER_BLOCK)  // 256

__global__ __launch_bounds__(THREADS)
void maskfiller_scatter_kernel(const float4* __restrict__ inputs,        // [B, K, D/4]
                               const int*    __restrict__ mask_ids,     // [B, M]
                               const int*    __restrict__ keep_ids,     // [B, K]
                               const float4* __restrict__ mask_emb,     // [D/4]
                               float4*       __restrict__ out)          // [B, L, D/4]
{
    // Each block handles ROWS_PER_BLOCK consecutive source rows.
    const int row = blockIdx.x * ROWS_PER_BLOCK + (threadIdx.x >> 7); // 0 .. B*L-1
    const int t   = threadIdx.x & (VEC4_PER_ROW - 1);                 // 0 .. 127

    const int b = row / L_DIM;
    const int r = row - b * L_DIM;       // 0 .. L-1

    if (r < K_DIM) {
        // keep row: copy inputs[b, r, :] -> out[b, keep_ids[b, r], :]
        const int dst = __ldg(&keep_ids[b * K_DIM + r]);
        const float4 v = inputs[((size_t)b * K_DIM + r) * VEC4_PER_ROW + t];
        out[((size_t)b * L_DIM + dst) * VEC4_PER_ROW + t] = v;
    } else {
        // mask row: broadcast embedding -> out[b, mask_ids[b, r-K], :]
        const int m   = r - K_DIM;
        const int dst = __ldg(&mask_ids[b * M_DIM + m]);
        const float4 v = __ldg(&mask_emb[t]);   // L1/L2 resident after first touch
        out[((size_t)b * L_DIM + dst) * VEC4_PER_ROW + t] = v;
    }
}

extern "C" void kernel_launch(void* const* d_in, const int* in_sizes, int n_in,
                              void* d_out, int out_size)
{
    // metadata order: inputs(f32), mask_position_ids(i32), keep_position_ids(i32),
    //                 mask_embedding(f32), [axis]
    const float4* inputs   = (const float4*)d_in[0];
    const int*    mask_ids = (const int*)d_in[1];
    const int*    keep_ids = (const int*)d_in[2];
    const float4* mask_emb = (const float4*)d_in[3];
    float4*       out      = (float4*)d_out;

    const int total_rows = B_DIM * L_DIM;                 // 65536
    const int blocks     = total_rows / ROWS_PER_BLOCK;   // 32768
    maskfiller_scatter_kernel<<<blocks, THREADS>>>(
        inputs, mask_ids, keep_ids, mask_emb, out);
}

// round 7
// speedup vs baseline: 1.1339x; 1.1339x over previous
#include <cuda_runtime.h>
#include <cuda_bf16.h>
#include <cstdint>

// Problem shape (fixed by the reference):
//   B=8, K=4096, M=4096, L=K+M=8192, D=512, fp32.
// out[b, keep_ids[b,k], :] = inputs[b,k,:]
// out[b, mask_ids[b,m], :] = mask_embedding[:]
// keep/mask ids partition [0, L) per batch -> every output row written exactly once.
//
// R3 layout: one WARP per 2KB row, 4 independent float4 per lane (MLP=4),
// 8 warps per block -> 8 rows/block, 8192 blocks. Streaming loads/stores
// (.cs) on the once-touched bulk data.

#define B_DIM 8
#define K_DIM 4096
#define M_DIM 4096
#define L_DIM (K_DIM + M_DIM)
#define D_DIM 512
#define VEC4_PER_ROW (D_DIM / 4)        // 128 float4 per row
#define ROWS_PER_BLOCK 8                // one warp per row
#define THREADS (32 * ROWS_PER_BLOCK)   // 256

__global__ __launch_bounds__(THREADS)
void maskfiller_scatter_kernel(const float4* __restrict__ inputs,        // [B, K, 128]
                               const int*    __restrict__ mask_ids,     // [B, M]
                               const int*    __restrict__ keep_ids,     // [B, K]
                               const float4* __restrict__ mask_emb,     // [128]
                               float4*       __restrict__ out)          // [B, L, 128]
{
    const int warp = threadIdx.x >> 5;                       // 0..7
    const int lane = threadIdx.x & 31;                       // 0..31
    const int row  = blockIdx.x * ROWS_PER_BLOCK + warp;     // 0 .. B*L-1

    const int b = row / L_DIM;
    const int r = row - b * L_DIM;                           // 0 .. L-1

    if (r < K_DIM) {
        // keep row: copy inputs[b, r, :] -> out[b, keep_ids[b, r], :]
        const int dst = __ldg(&keep_ids[b * K_DIM + r]);     // warp-uniform, L1/L2 hit
        const float4* src = inputs + ((size_t)b * K_DIM + r) * VEC4_PER_ROW + lane;
        float4*       dp  = out    + ((size_t)b * L_DIM + dst) * VEC4_PER_ROW + lane;

        // 4 independent 16B loads front-batched -> MLP=4 per thread
        float4 v0 = __ldcs(src + 0);
        float4 v1 = __ldcs(src + 32);
        float4 v2 = __ldcs(src + 64);
        float4 v3 = __ldcs(src + 96);
        __stcs(dp + 0,  v0);
        __stcs(dp + 32, v1);
        __stcs(dp + 64, v2);
        __stcs(dp + 96, v3);
    } else {
        // mask row: broadcast embedding -> out[b, mask_ids[b, r-K], :]
        const int m   = r - K_DIM;
        const int dst = __ldg(&mask_ids[b * M_DIM + m]);
        float4* dp = out + ((size_t)b * L_DIM + dst) * VEC4_PER_ROW + lane;

        // embedding is hot (reused by 4096*B rows) -> keep cached
        float4 v0 = __ldg(mask_emb + lane + 0);
        float4 v1 = __ldg(mask_emb + lane + 32);
        float4 v2 = __ldg(mask_emb + lane + 64);
        float4 v3 = __ldg(mask_emb + lane + 96);
        __stcs(dp + 0,  v0);
        __stcs(dp + 32, v1);
        __stcs(dp + 64, v2);
        __stcs(dp + 96, v3);
    }
}

extern "C" void kernel_launch(void* const* d_in, const int* in_sizes, int n_in,
                              void* d_out, int out_size)
{
    // metadata order: inputs(f32), mask_position_ids(i32), keep_position_ids(i32),
    //                 mask_embedding(f32), [axis]
    const float4* inputs   = (const float4*)d_in[0];
    const int*    mask_ids = (const int*)d_in[1];
    const int*    keep_ids = (const int*)d_in[2];
    const float4* mask_emb = (const float4*)d_in[3];
    float4*       out      = (float4*)d_out;

    const int total_rows = B_DIM * L_DIM;                  // 65536
    const int blocks     = total_rows / ROWS_PER_BLOCK;    // 8192
    maskfiller_scatter_kernel<<<blocks, THREADS>>>(
        inputs, mask_ids, keep_ids, mask_emb, out);
}